// round 5
// baseline (speedup 1.0000x reference)
#include <cuda_runtime.h>

#define T_STEPS 512
#define HDIM    64
#define PAIRS   4                    // warp-pairs per block
#define BPP     2                    // batches per pair
#define BPB     (PAIRS * BPP)        // 8 batches per block
#define NTHREADS 256

// ---------- packed fp32x2 helpers (sm_100+ PTX) ----------
__device__ __forceinline__ unsigned long long pack2f(float lo, float hi) {
    unsigned long long r;
    asm("mov.b64 %0, {%1, %2};" : "=l"(r) : "f"(lo), "f"(hi));
    return r;
}
__device__ __forceinline__ void unpack2f(unsigned long long v, float& lo, float& hi) {
    asm("mov.b64 {%0, %1}, %2;" : "=f"(lo), "=f"(hi) : "l"(v));
}
__device__ __forceinline__ unsigned long long ffma2(unsigned long long a,
                                                    unsigned long long b,
                                                    unsigned long long c) {
    unsigned long long d;
    asm("fma.rn.f32x2 %0, %1, %2, %3;" : "=l"(d) : "l"(a), "l"(b), "l"(c));
    return d;
}
__device__ __forceinline__ unsigned long long fadd2(unsigned long long a,
                                                    unsigned long long b) {
    unsigned long long d;
    asm("add.rn.f32x2 %0, %1, %2;" : "=l"(d) : "l"(a), "l"(b));
    return d;
}
__device__ __forceinline__ unsigned smem_u32(const void* p) {
    return (unsigned)__cvta_generic_to_shared(p);
}
__device__ __forceinline__ float fast_tanh(float a) {
    // tanh(a) = 1 - 2/(e^{2a}+1); exact at +/-inf, ~1e-7 rel err via MUFU
    float e = __expf(2.0f * a);
    return 1.0f - __fdividef(2.0f, e + 1.0f);
}

// One recurrence step: this lane's single row, for 2 batches. 8 indep chains.
__device__ __forceinline__ void step2(float xA, float xB,
                                      unsigned aA, unsigned aB,
                                      const unsigned long long* wr,
                                      float bias, float wi,
                                      float& hA, float& hB) {
    unsigned long long cA0 = 0ull, cA1 = 0ull, cA2 = 0ull, cA3 = 0ull;
    unsigned long long cB0 = 0ull, cB1 = 0ull, cB2 = 0ull, cB3 = 0ull;
#pragma unroll
    for (int k = 0; k < 8; k++) {
        unsigned long long pA0, pA1, pA2, pA3, pB0, pB1, pB2, pB3;
        asm volatile("ld.shared.v2.b64 {%0,%1}, [%2];"
                     : "=l"(pA0), "=l"(pA1) : "r"(aA + 32 * k));
        asm volatile("ld.shared.v2.b64 {%0,%1}, [%2];"
                     : "=l"(pA2), "=l"(pA3) : "r"(aA + 32 * k + 16));
        asm volatile("ld.shared.v2.b64 {%0,%1}, [%2];"
                     : "=l"(pB0), "=l"(pB1) : "r"(aB + 32 * k));
        asm volatile("ld.shared.v2.b64 {%0,%1}, [%2];"
                     : "=l"(pB2), "=l"(pB3) : "r"(aB + 32 * k + 16));
        cA0 = ffma2(wr[4 * k    ], pA0, cA0);
        cA1 = ffma2(wr[4 * k + 1], pA1, cA1);
        cA2 = ffma2(wr[4 * k + 2], pA2, cA2);
        cA3 = ffma2(wr[4 * k + 3], pA3, cA3);
        cB0 = ffma2(wr[4 * k    ], pB0, cB0);
        cB1 = ffma2(wr[4 * k + 1], pB1, cB1);
        cB2 = ffma2(wr[4 * k + 2], pB2, cB2);
        cB3 = ffma2(wr[4 * k + 3], pB3, cB3);
    }
    float l, u;
    unsigned long long sA = fadd2(fadd2(cA0, cA1), fadd2(cA2, cA3));
    unsigned long long sB = fadd2(fadd2(cB0, cB1), fadd2(cB2, cB3));
    unpack2f(sA, l, u); hA = fast_tanh(fmaf(wi, xA, bias) + l + u);
    unpack2f(sB, l, u); hB = fast_tanh(fmaf(wi, xB, bias) + l + u);
}

__global__ __launch_bounds__(NTHREADS, 2)
void rnn_kernel(const float* __restrict__ x,
                const float* __restrict__ W_ih,
                const float* __restrict__ W_hh,
                const float* __restrict__ b_ih,
                const float* __restrict__ b_hh,
                const float* __restrict__ fc_w,
                const float* __restrict__ fc_b,
                float* __restrict__ out) {
    __shared__ float xs[BPB][T_STEPS];        // staged x rows (16 KB)
    __shared__ float hbuf[2][BPB][HDIM];      // double-buffered hidden state (4 KB)
    __shared__ float red[BPB][2];             // fc partial sums per half

    const int tid  = threadIdx.x;
    const int w    = tid >> 5;
    const int lane = tid & 31;
    const int pair = w >> 1;                  // warp-pair index (0..3)
    const int half = w & 1;                   // which 32 rows this warp owns
    const int r    = half * 32 + lane;        // the single row this lane owns
    const int gA   = pair * 2;                // batch slots within block
    const int gB   = gA + 1;
    const int bA   = blockIdx.x * BPB + gA;
    const int bB   = blockIdx.x * BPB + gB;

    // Stage x for the 8 batches of this block (coalesced float4)
    {
        const float4* src = (const float4*)(x + (size_t)blockIdx.x * BPB * T_STEPS);
        float4* dst = (float4*)&xs[0][0];
        for (int idx = tid; idx < BPB * T_STEPS / 4; idx += NTHREADS)
            dst[idx] = src[idx];
    }

    // This lane's W_hh row: 32 f32x2 registers (64 regs)
    unsigned long long wr[32];
#pragma unroll
    for (int j = 0; j < 16; j++) {
        float4 v = __ldg((const float4*)(W_hh + (size_t)r * HDIM + 4 * j));
        wr[2 * j]     = pack2f(v.x, v.y);
        wr[2 * j + 1] = pack2f(v.z, v.w);
    }
    const float bias = b_ih[r] + b_hh[r];
    const float wi   = W_ih[r];
    const float fw   = fc_w[r];

    // h0 = 0
    hbuf[0][gA][r] = 0.0f;
    hbuf[0][gB][r] = 0.0f;
    __syncthreads();   // covers x staging + h init

    const unsigned hA0b = smem_u32(&hbuf[0][gA][0]);
    const unsigned hA1b = smem_u32(&hbuf[1][gA][0]);
    const unsigned hB0b = smem_u32(&hbuf[0][gB][0]);
    const unsigned hB1b = smem_u32(&hbuf[1][gB][0]);
    const unsigned stA0 = hA0b + 4 * r;       // this lane's scalar slot
    const unsigned stA1 = hA1b + 4 * r;
    const unsigned stB0 = hB0b + 4 * r;
    const unsigned stB1 = hB1b + 4 * r;
    const int barid = pair + 1;               // named barrier per warp-pair

    float hA = 0.0f, hB = 0.0f;
    for (int t = 0; t < T_STEPS; t += 2) {
        step2(xs[gA][t], xs[gB][t], hA0b, hB0b, wr, bias, wi, hA, hB);
        asm volatile("st.shared.f32 [%0], %1;" :: "r"(stA1), "f"(hA));
        asm volatile("st.shared.f32 [%0], %1;" :: "r"(stB1), "f"(hB));
        asm volatile("bar.sync %0, 64;" :: "r"(barid) : "memory");
        step2(xs[gA][t + 1], xs[gB][t + 1], hA1b, hB1b, wr, bias, wi, hA, hB);
        asm volatile("st.shared.f32 [%0], %1;" :: "r"(stA0), "f"(hA));
        asm volatile("st.shared.f32 [%0], %1;" :: "r"(stB0), "f"(hB));
        asm volatile("bar.sync %0, 64;" :: "r"(barid) : "memory");
    }

    // fc head: butterfly within warp (32 rows), combine halves via smem
    float vA = hA * fw;
    float vB = hB * fw;
#pragma unroll
    for (int off = 16; off > 0; off >>= 1) {
        vA += __shfl_xor_sync(0xFFFFFFFFu, vA, off);
        vB += __shfl_xor_sync(0xFFFFFFFFu, vB, off);
    }
    if (lane == 0) { red[gA][half] = vA; red[gB][half] = vB; }
    __syncthreads();
    if (tid < BPB)
        out[blockIdx.x * BPB + tid] = red[tid][0] + red[tid][1] + fc_b[0];
}

extern "C" void kernel_launch(void* const* d_in, const int* in_sizes, int n_in,
                              void* d_out, int out_size) {
    const float* x    = (const float*)d_in[0];
    const float* W_ih = (const float*)d_in[1];
    const float* W_hh = (const float*)d_in[2];
    const float* b_ih = (const float*)d_in[3];
    const float* b_hh = (const float*)d_in[4];
    const float* fc_w = (const float*)d_in[5];
    const float* fc_b = (const float*)d_in[6];
    float* out = (float*)d_out;

    int B = in_sizes[0] / T_STEPS;     // I = 1
    int grid = B / BPB;                // 2048/8 = 256 blocks, 2 CTAs/SM
    rnn_kernel<<<grid, NTHREADS>>>(x, W_ih, W_hh, b_ih, b_hh, fc_w, fc_b, out);
}